// round 13
// baseline (speedup 1.0000x reference)
#include <cuda_runtime.h>
#include <cuda_fp16.h>
#include <math.h>

// Problem constants (fixed shapes)
#define kN    50000
#define kE    800000
#define kIN   128
#define kH1   8
#define kHID1 256
#define kHID2 128
#define kFC1  512

// ---------------- device globals: TOTAL = 5.4 MB -----------------------------
__device__ float g_acc[kN * 16];   // 3.2 MB — 16-col aggregation accumulator (both layers)
__device__ float g_d1[kN * kH1];   // 1.6 MB — layer-1 softmax denominators
__device__ float g_as2[kN];        // 0.2 MB
__device__ float g_ad2[kN];        // 0.2 MB
__device__ float g_d2[kN];         // 0.2 MB

// d_out layout: out [kN] | alpha1 region [kE*8 floats = 25.6MB] | alpha2 region [kE floats = 3.2MB]
// alpha1 region (as fp16 [kN][256] = exactly 25.6MB):
//   h1 -> x1 (in-place per 16-col pass) -> h2 (cols [0:128), in-place row-local)
//   + x2 (cols [128:256)) -> finally overwritten with alpha1 fp32 values.
// alpha2 region (as fp32 [kN][16] = exactly 3.2MB): as1 (8) | ad1 (8) per node,
//   finally overwritten with alpha2 values.

// ---------------- helpers ---------------------------------------------------
__device__ __forceinline__ void redAdd4(float* p, float a, float b, float c, float d) {
    asm volatile("red.global.add.v4.f32 [%0], {%1,%2,%3,%4};"
                 :: "l"(p), "f"(a), "f"(b), "f"(c), "f"(d) : "memory");
}
__device__ __forceinline__ float lrelu(float v) { return v > 0.f ? v : 0.2f * v; }

// ---------------- init -------------------------------------------------------
__global__ __launch_bounds__(256) void init_kernel() {
    int i = blockIdx.x * blockDim.x + threadIdx.x;
    int stride = gridDim.x * blockDim.x;
    for (int t = i; t < kN * 16; t += stride) g_acc[t] = 0.f;
    for (int t = i; t < kN * kH1; t += stride) g_d1[t] = 0.f;
    for (int t = i; t < kN; t += stride) g_d2[t] = 0.f;
}

// ---------------- GEMM1: h1 = x @ W1 (fp16) + fused as1/ad1 into SA ----------
// 256 threads (one per col), 8 rows/block; warp == head.
__global__ __launch_bounds__(256) void gemm1_kernel(const float* __restrict__ x,
                                                    const float* __restrict__ W1,
                                                    const float* __restrict__ att_s,
                                                    const float* __restrict__ att_d,
                                                    __half* __restrict__ R16,
                                                    float* __restrict__ SA, int n) {
    const int BM = 8, K = kIN, CO = kHID1;
    __shared__ float As[BM * K];
    const int tid = threadIdx.x;
    const int row0 = blockIdx.x * BM;
    {
        int m = tid / (K / 4), c = tid % (K / 4);
        int r = row0 + m;
        float4 v = make_float4(0.f, 0.f, 0.f, 0.f);
        if (r < n) v = ((const float4*)x)[(size_t)r * (K / 4) + c];
        ((float4*)As)[tid] = v;
    }
    __syncthreads();

    float acc[BM];
#pragma unroll
    for (int m = 0; m < BM; m++) acc[m] = 0.f;
    for (int k = 0; k < K; k += 4) {
        float w0 = W1[(k + 0) * CO + tid];
        float w1 = W1[(k + 1) * CO + tid];
        float w2 = W1[(k + 2) * CO + tid];
        float w3 = W1[(k + 3) * CO + tid];
#pragma unroll
        for (int m = 0; m < BM; m++) {
            float4 a = *(const float4*)&As[m * K + k];
            acc[m] = fmaf(a.x, w0, acc[m]);
            acc[m] = fmaf(a.y, w1, acc[m]);
            acc[m] = fmaf(a.z, w2, acc[m]);
            acc[m] = fmaf(a.w, w3, acc[m]);
        }
    }
    const int lane = tid & 31, head = tid >> 5;
    const float asw = att_s[tid], adw = att_d[tid];
#pragma unroll
    for (int m = 0; m < BM; m++) {
        int r = row0 + m;
        float a = acc[m];
        float s = a * asw, d = a * adw;
#pragma unroll
        for (int o = 16; o > 0; o >>= 1) {
            s += __shfl_xor_sync(0xffffffffu, s, o);
            d += __shfl_xor_sync(0xffffffffu, d, o);
        }
        if (r < n) {
            if (lane == 0) { SA[r * 16 + head] = s; SA[r * 16 + 8 + head] = d; }
            R16[(size_t)r * kHID1 + tid] = __float2half(a);
        }
    }
}

// ---------------- layer-1 denominators (no max pass: scores O(1)) ------------
__global__ __launch_bounds__(256) void edge1_sum_kernel(const int* __restrict__ ei,
                                                        const float* __restrict__ SA) {
    int e = blockIdx.x * blockDim.x + threadIdx.x;
    if (e >= kE) return;
    int src = ei[e], dst = ei[kE + e];
    float4 as0 = ((const float4*)(SA + src * 16))[0];
    float4 as1 = ((const float4*)(SA + src * 16))[1];
    float4 ad0 = ((const float4*)(SA + dst * 16 + 8))[0];
    float4 ad1 = ((const float4*)(SA + dst * 16 + 8))[1];
    redAdd4(g_d1 + dst * 8,
            expf(lrelu(as0.x + ad0.x)), expf(lrelu(as0.y + ad0.y)),
            expf(lrelu(as0.z + ad0.z)), expf(lrelu(as0.w + ad0.w)));
    redAdd4(g_d1 + dst * 8 + 4,
            expf(lrelu(as1.x + ad1.x)), expf(lrelu(as1.y + ad1.y)),
            expf(lrelu(as1.z + ad1.z)), expf(lrelu(as1.w + ad1.w)));
}

// ---------------- layer-1 aggregation pass p (16 cols of head p>>1) ----------
// 4 threads per edge; thread t covers 4 cols.
__global__ __launch_bounds__(256) void agg1_kernel(const int* __restrict__ ei,
                                                   const __half* __restrict__ R16,
                                                   const float* __restrict__ SA, int p) {
    int g = blockIdx.x * blockDim.x + threadIdx.x;
    int e = g >> 2, t = g & 3;
    if (e >= kE) return;
    int src = ei[e], dst = ei[kE + e];
    int head = p >> 1;
    int colbase = head * 32 + (p & 1) * 16;
    float s = lrelu(SA[src * 16 + head] + SA[dst * 16 + 8 + head]);
    float alpha = expf(s) / (g_d1[dst * 8 + head] + 1e-16f);
    uint2 hv = *(const uint2*)(R16 + (size_t)src * kHID1 + colbase + 4 * t);
    float2 f0 = __half22float2(*(const __half2*)&hv.x);
    float2 f1 = __half22float2(*(const __half2*)&hv.y);
    redAdd4(g_acc + dst * 16 + 4 * t,
            f0.x * alpha, f0.y * alpha, f1.x * alpha, f1.y * alpha);
}

// finalize pass p: x1 cols = elu(acc + b1), fp16 over dead h1 cols; re-zero acc
__global__ __launch_bounds__(256) void fin1_kernel(const float* __restrict__ b1,
                                                   __half* __restrict__ R16, int p) {
    int head = p >> 1;
    int colbase = head * 32 + (p & 1) * 16;
    int i = blockIdx.x * blockDim.x + threadIdx.x;
    int stride = gridDim.x * blockDim.x;
    for (int t = i; t < kN * 16; t += stride) {
        int n = t >> 4, c = t & 15;
        float v = g_acc[t] + b1[colbase + c];
        v = v > 0.f ? v : expm1f(v);
        R16[(size_t)n * kHID1 + colbase + c] = __float2half(v);
        g_acc[t] = 0.f;
    }
}

// ---------------- GEMM2: h2 = x1 @ W2; h2 fp16 overwrites own rows' cols[0:128)
__global__ __launch_bounds__(128) void gemm2_kernel(__half* __restrict__ R16,
                                                    const float* __restrict__ W2,
                                                    const float* __restrict__ att_s,
                                                    const float* __restrict__ att_d, int n) {
    const int BM = 8, K = kHID1, CO = kHID2;
    __shared__ __half As[BM * K];
    __shared__ float redS[4][BM], redD[4][BM];
    const int tid = threadIdx.x;
    const int row0 = blockIdx.x * BM;
    for (int i = tid; i < BM * (K / 8); i += 128) {
        int m = i / (K / 8), c = i % (K / 8);
        int r = row0 + m;
        float4 v = make_float4(0.f, 0.f, 0.f, 0.f);
        if (r < n) v = *(const float4*)(R16 + (size_t)r * K + c * 8);
        ((float4*)As)[i] = v;
    }
    __syncthreads();

    float acc[BM];
#pragma unroll
    for (int m = 0; m < BM; m++) acc[m] = 0.f;
    for (int k2 = 0; k2 < K / 2; k2++) {
        float w0 = W2[(2 * k2 + 0) * CO + tid];
        float w1 = W2[(2 * k2 + 1) * CO + tid];
#pragma unroll
        for (int m = 0; m < BM; m++) {
            float2 a = __half22float2(*(const __half2*)&As[m * K + 2 * k2]);
            acc[m] = fmaf(a.x, w0, acc[m]);
            acc[m] = fmaf(a.y, w1, acc[m]);
        }
    }
    const int lane = tid & 31, warp = tid >> 5;
    const float asw = att_s[tid], adw = att_d[tid];
#pragma unroll
    for (int m = 0; m < BM; m++) {
        float s = acc[m] * asw, d = acc[m] * adw;
#pragma unroll
        for (int o = 16; o > 0; o >>= 1) {
            s += __shfl_xor_sync(0xffffffffu, s, o);
            d += __shfl_xor_sync(0xffffffffu, d, o);
        }
        if (lane == 0) { redS[warp][m] = s; redD[warp][m] = d; }
    }
    __syncthreads();
    if (tid < BM) {
        int r = row0 + tid;
        if (r < n) {
            g_as2[r] = redS[0][tid] + redS[1][tid] + redS[2][tid] + redS[3][tid];
            g_ad2[r] = redD[0][tid] + redD[1][tid] + redD[2][tid] + redD[3][tid];
        }
    }
#pragma unroll
    for (int m = 0; m < BM; m++) {
        int r = row0 + m;
        if (r < n) R16[(size_t)r * kHID1 + tid] = __float2half(acc[m]);   // h2 over x1 (own rows)
    }
}

// ---------------- layer-2 denominator ---------------------------------------
__global__ __launch_bounds__(256) void edge2_sum_kernel(const int* __restrict__ ei) {
    int e = blockIdx.x * blockDim.x + threadIdx.x;
    if (e >= kE) return;
    int src = ei[e], dst = ei[kE + e];
    atomicAdd(&g_d2[dst], expf(lrelu(g_as2[src] + g_ad2[dst])));
}

// ---------------- layer-2 aggregation pass p (cols 16p..16p+16) --------------
__global__ __launch_bounds__(256) void agg2_kernel(const int* __restrict__ ei,
                                                   const __half* __restrict__ R16, int p) {
    int g = blockIdx.x * blockDim.x + threadIdx.x;
    int e = g >> 2, t = g & 3;
    if (e >= kE) return;
    int src = ei[e], dst = ei[kE + e];
    float s = lrelu(g_as2[src] + g_ad2[dst]);
    float alpha = expf(s) / (g_d2[dst] + 1e-16f);
    uint2 hv = *(const uint2*)(R16 + (size_t)src * kHID1 + p * 16 + 4 * t);
    float2 f0 = __half22float2(*(const __half2*)&hv.x);
    float2 f1 = __half22float2(*(const __half2*)&hv.y);
    redAdd4(g_acc + dst * 16 + 4 * t,
            f0.x * alpha, f0.y * alpha, f1.x * alpha, f1.y * alpha);
}

// finalize pass p: x2 cols = relu(acc + b2) fp16 -> cols [128+16p ..); re-zero acc
__global__ __launch_bounds__(256) void fin2_kernel(const float* __restrict__ b2,
                                                   __half* __restrict__ R16, int p) {
    int i = blockIdx.x * blockDim.x + threadIdx.x;
    int stride = gridDim.x * blockDim.x;
    for (int t = i; t < kN * 16; t += stride) {
        int n = t >> 4, c = t & 15;
        float v = g_acc[t] + b2[p * 16 + c];
        v = v > 0.f ? v : 0.f;
        R16[(size_t)n * kHID1 + 128 + p * 16 + c] = __float2half(v);
        g_acc[t] = 0.f;
    }
}

// ---------------- fused FC head: out = relu(x2@fcW1+fcb1)@fcW2+fcb2 ----------
// x2 fp16 at R16 + r*256 + 128 (128 halves per row).
__global__ __launch_bounds__(512) void fc_kernel(const __half* __restrict__ R16,
                                                 const float* __restrict__ fcW1,
                                                 const float* __restrict__ fcb1,
                                                 const float* __restrict__ fcW2,
                                                 const float* __restrict__ fcb2,
                                                 float* __restrict__ out) {
    const int BM = 8;
    __shared__ float Xs[BM * kHID2];
    __shared__ float wsum[16][BM];
    const int tid = threadIdx.x;
    const int row0 = blockIdx.x * BM;

    if (tid < BM * (kHID2 / 8)) {          // 128 loaders, 8 halves each
        int m = tid / (kHID2 / 8), c = tid % (kHID2 / 8);
        int r = row0 + m;
        float4 raw = make_float4(0.f, 0.f, 0.f, 0.f);
        if (r < kN) raw = *(const float4*)(R16 + (size_t)r * kHID1 + 128 + c * 8);
        const __half2* hp = (const __half2*)&raw;
#pragma unroll
        for (int j = 0; j < 4; j++) {
            float2 f = __half22float2(hp[j]);
            Xs[m * kHID2 + c * 8 + 2 * j]     = f.x;
            Xs[m * kHID2 + c * 8 + 2 * j + 1] = f.y;
        }
    }
    __syncthreads();

    float acc[BM];
#pragma unroll
    for (int m = 0; m < BM; m++) acc[m] = 0.f;
    for (int k = 0; k < kHID2; k += 4) {
        float w0 = fcW1[(k + 0) * kFC1 + tid];
        float w1 = fcW1[(k + 1) * kFC1 + tid];
        float w2 = fcW1[(k + 2) * kFC1 + tid];
        float w3 = fcW1[(k + 3) * kFC1 + tid];
#pragma unroll
        for (int m = 0; m < BM; m++) {
            float4 a = *(const float4*)&Xs[m * kHID2 + k];
            acc[m] = fmaf(a.x, w0, acc[m]);
            acc[m] = fmaf(a.y, w1, acc[m]);
            acc[m] = fmaf(a.z, w2, acc[m]);
            acc[m] = fmaf(a.w, w3, acc[m]);
        }
    }
    float c = fcW2[tid], bb = fcb1[tid];
    const int warp = tid >> 5, lane = tid & 31;
#pragma unroll
    for (int m = 0; m < BM; m++) {
        float p = fmaxf(acc[m] + bb, 0.f) * c;
#pragma unroll
        for (int o = 16; o > 0; o >>= 1) p += __shfl_xor_sync(0xffffffffu, p, o);
        if (lane == 0) wsum[warp][m] = p;
    }
    __syncthreads();
    if (tid < BM) {
        float s = fcb2[0];
#pragma unroll
        for (int w = 0; w < 16; w++) s += wsum[w][tid];
        int r = row0 + tid;
        if (r < kN) out[r] = s;
    }
}

// ---------------- final alpha writes -----------------------------------------
// alpha1 first (needs SA, which alpha2_write will overwrite afterwards).
__global__ __launch_bounds__(256) void alpha1_write_kernel(const int* __restrict__ ei,
                                                           const float* __restrict__ SA,
                                                           float* __restrict__ alpha1) {
    int e = blockIdx.x * blockDim.x + threadIdx.x;
    if (e >= kE) return;
    int src = ei[e], dst = ei[kE + e];
    float4 as0 = ((const float4*)(SA + src * 16))[0];
    float4 as1 = ((const float4*)(SA + src * 16))[1];
    float4 ad0 = ((const float4*)(SA + dst * 16 + 8))[0];
    float4 ad1 = ((const float4*)(SA + dst * 16 + 8))[1];
    float4 d0 = ((const float4*)(g_d1 + dst * 8))[0];
    float4 d1 = ((const float4*)(g_d1 + dst * 8))[1];
    float4 r0, r1;
    r0.x = expf(lrelu(as0.x + ad0.x)) / (d0.x + 1e-16f);
    r0.y = expf(lrelu(as0.y + ad0.y)) / (d0.y + 1e-16f);
    r0.z = expf(lrelu(as0.z + ad0.z)) / (d0.z + 1e-16f);
    r0.w = expf(lrelu(as0.w + ad0.w)) / (d0.w + 1e-16f);
    r1.x = expf(lrelu(as1.x + ad1.x)) / (d1.x + 1e-16f);
    r1.y = expf(lrelu(as1.y + ad1.y)) / (d1.y + 1e-16f);
    r1.z = expf(lrelu(as1.z + ad1.z)) / (d1.z + 1e-16f);
    r1.w = expf(lrelu(as1.w + ad1.w)) / (d1.w + 1e-16f);
    ((float4*)(alpha1 + (size_t)e * 8))[0] = r0;
    ((float4*)(alpha1 + (size_t)e * 8))[1] = r1;
}

__global__ __launch_bounds__(256) void alpha2_write_kernel(const int* __restrict__ ei,
                                                           float* __restrict__ alpha2) {
    int e = blockIdx.x * blockDim.x + threadIdx.x;
    if (e >= kE) return;
    int src = ei[e], dst = ei[kE + e];
    float s = lrelu(g_as2[src] + g_ad2[dst]);
    alpha2[e] = expf(s) / (g_d2[dst] + 1e-16f);
}

// ---------------- launch ----------------------------------------------------
extern "C" void kernel_launch(void* const* d_in, const int* in_sizes, int n_in,
                              void* d_out, int out_size) {
    const float* x        = (const float*)d_in[0];
    const int*   ei       = (const int*)d_in[1];
    const float* W1       = (const float*)d_in[2];
    const float* att_src1 = (const float*)d_in[3];
    const float* att_dst1 = (const float*)d_in[4];
    const float* b1       = (const float*)d_in[5];
    const float* W2       = (const float*)d_in[6];
    const float* att_src2 = (const float*)d_in[7];
    const float* att_dst2 = (const float*)d_in[8];
    const float* b2       = (const float*)d_in[9];
    const float* fcW1     = (const float*)d_in[10];
    const float* fcb1     = (const float*)d_in[11];
    const float* fcW2     = (const float*)d_in[12];
    const float* fcb2     = (const float*)d_in[13];

    float* out_o  = (float*)d_out;                        // [N]
    float* alpha1 = (float*)d_out + kN;                   // [E,8] scratch until end
    float* alpha2 = (float*)d_out + kN + (size_t)kE * 8;  // [E]   holds SA until end
    __half* R16   = (__half*)alpha1;                      // fp16 [kN,256] staging
    float*  SA    = alpha2;                               // fp32 [kN,16] as1|ad1

    const int TPB = 256;
    const int edge_blocks = (kE + TPB - 1) / TPB;          // thread per edge
    const int aggp_blocks = (kE * 4 + TPB - 1) / TPB;      // 4 threads per edge
    const int nrow_blocks = (kN + 7) / 8;

    init_kernel<<<1024, TPB>>>();

    // ---- layer 1 ----
    gemm1_kernel<<<nrow_blocks, 256>>>(x, W1, att_src1, att_dst1, R16, SA, kN);
    edge1_sum_kernel<<<edge_blocks, TPB>>>(ei, SA);
    for (int p = 0; p < 16; p++) {
        agg1_kernel<<<aggp_blocks, TPB>>>(ei, R16, SA, p);
        fin1_kernel<<<1024, TPB>>>(b1, R16, p);    // also re-zeros g_acc
    }

    // ---- layer 2 (R16 holds x1 fp16; gemm2 overwrites cols[0:128) with h2) ----
    gemm2_kernel<<<nrow_blocks, 128>>>(R16, W2, att_src2, att_dst2, kN);
    edge2_sum_kernel<<<edge_blocks, TPB>>>(ei);
    for (int p = 0; p < 8; p++) {
        agg2_kernel<<<aggp_blocks, TPB>>>(ei, R16, p);
        fin2_kernel<<<1024, TPB>>>(b2, R16, p);    // x2 -> cols [128+16p), re-zeros g_acc
    }

    // ---- FC head ----
    fc_kernel<<<nrow_blocks, 512>>>(R16, fcW1, fcb1, fcW2, fcb2, out_o);

    // ---- final alpha outputs (alpha1 before alpha2: alpha1 needs SA) ----
    alpha1_write_kernel<<<edge_blocks, TPB>>>(ei, SA, alpha1);
    alpha2_write_kernel<<<edge_blocks, TPB>>>(ei, alpha2);
}

// round 14
// speedup vs baseline: 1.3406x; 1.3406x over previous
#include <cuda_runtime.h>
#include <cuda_fp16.h>
#include <math.h>

// Problem constants (fixed shapes)
#define kN    50000
#define kE    800000
#define kIN   128
#define kH1   8
#define kHID1 256
#define kHID2 128
#define kFC1  512
#define SCAN_B 196   // ceil(kN/256)

// ---------------- device globals: TOTAL = 7.4 MB -----------------------------
__device__ unsigned short g_src16[kE];     // 1.6 MB  CSR src ids (kN < 65536)
__device__ int   g_cnt[kN];                // 0.2 MB  histogram -> fill cursor
__device__ int   g_rowptr[kN + 1];         // 0.2 MB  CSR row pointers
__device__ int   g_bsum[SCAN_B];           //         scan block sums
__device__ float g_d1[kN * kH1];           // 1.6 MB  layer-1 denominators
__device__ float g_as2[kN];                // 0.6 MB  layer-2 scores + denom
__device__ float g_ad2[kN];
__device__ float g_d2[kN];
__device__ __align__(16) __half g_x1a[kN * 32];  // 3.2 MB spare slice (x1 head 0)

// d_out layout: out [kN] | alpha1 region [kE*8 f32 = 25.6MB] | alpha2 region [kE f32 = 3.2MB]
// alpha1 region as fp16 R16[kN][256]: h1 -> x1 (staged, slices shifted down one
//   32-col slot; head0 slice in g_x1a) -> h2 (cols [0:128)) + x2 (cols [128:256))
//   -> finally alpha1 fp32.
// alpha2 region as fp32 SA[kN][16]: as1[8] | ad1[8] -> finally alpha2.

// ---------------- helpers ---------------------------------------------------
__device__ __forceinline__ float lrelu(float v) { return v > 0.f ? v : 0.2f * v; }

// ---------------- init: zero histogram --------------------------------------
__global__ __launch_bounds__(256) void init_cnt_kernel() {
    int i = blockIdx.x * blockDim.x + threadIdx.x;
    if (i < kN) g_cnt[i] = 0;
}

// ---------------- CSR build --------------------------------------------------
__global__ __launch_bounds__(256) void hist_kernel(const int* __restrict__ ei) {
    int e = blockIdx.x * blockDim.x + threadIdx.x;
    if (e >= kE) return;
    atomicAdd(&g_cnt[ei[kE + e]], 1);
}

__global__ __launch_bounds__(256) void scan1_kernel() {
    __shared__ int s[256];
    int t = threadIdx.x;
    int i = blockIdx.x * 256 + t;
    int v = (i < kN) ? g_cnt[i] : 0;
    s[t] = v; __syncthreads();
#pragma unroll
    for (int off = 1; off < 256; off <<= 1) {
        int x = (t >= off) ? s[t - off] : 0; __syncthreads();
        s[t] += x; __syncthreads();
    }
    if (i < kN) g_rowptr[i] = s[t] - v;        // block-local exclusive
    if (t == 255) g_bsum[blockIdx.x] = s[255]; // block total
}

__global__ __launch_bounds__(256) void scan2_kernel() {
    __shared__ int s[256];
    int t = threadIdx.x;
    int v = (t < SCAN_B) ? g_bsum[t] : 0;
    s[t] = v; __syncthreads();
#pragma unroll
    for (int off = 1; off < 256; off <<= 1) {
        int x = (t >= off) ? s[t - off] : 0; __syncthreads();
        s[t] += x; __syncthreads();
    }
    if (t < SCAN_B) g_bsum[t] = s[t] - v;      // exclusive block offsets
}

__global__ __launch_bounds__(256) void scan3_kernel() {
    int i = blockIdx.x * 256 + threadIdx.x;
    if (i < kN) {
        int val = g_rowptr[i] + g_bsum[blockIdx.x];
        g_rowptr[i] = val;
        g_cnt[i] = val;                        // fill cursor
    }
    if (i == 0) g_rowptr[kN] = kE;
}

__global__ __launch_bounds__(256) void fill_kernel(const int* __restrict__ ei) {
    int e = blockIdx.x * blockDim.x + threadIdx.x;
    if (e >= kE) return;
    int src = ei[e], dst = ei[kE + e];
    int pos = atomicAdd(&g_cnt[dst], 1);
    g_src16[pos] = (unsigned short)src;
}

// ---------------- GEMM1: h1 = x @ W1 (fp16) + fused as1/ad1 into SA ----------
// BM=32 rows/block, 256 threads (one per output col); warp == head.
__global__ __launch_bounds__(256) void gemm1_kernel(const float* __restrict__ x,
                                                    const float* __restrict__ W1,
                                                    const float* __restrict__ att_s,
                                                    const float* __restrict__ att_d,
                                                    __half* __restrict__ R16,
                                                    float* __restrict__ SA) {
    const int BM = 32, K = kIN, CO = kHID1;
    __shared__ float As[BM * K];   // 16 KB
    const int tid = threadIdx.x;
    const int row0 = blockIdx.x * BM;
    for (int i = tid; i < BM * (K / 4); i += 256) {
        int m = i / (K / 4), c = i % (K / 4);
        int r = row0 + m;
        float4 v = make_float4(0.f, 0.f, 0.f, 0.f);
        if (r < kN) v = ((const float4*)x)[(size_t)r * (K / 4) + c];
        ((float4*)As)[i] = v;
    }
    __syncthreads();

    float acc[BM];
#pragma unroll
    for (int m = 0; m < BM; m++) acc[m] = 0.f;
    for (int k = 0; k < K; k += 4) {
        float w0 = W1[(k + 0) * CO + tid];
        float w1 = W1[(k + 1) * CO + tid];
        float w2 = W1[(k + 2) * CO + tid];
        float w3 = W1[(k + 3) * CO + tid];
#pragma unroll
        for (int m = 0; m < BM; m++) {
            float4 a = *(const float4*)&As[m * K + k];
            acc[m] = fmaf(a.x, w0, acc[m]);
            acc[m] = fmaf(a.y, w1, acc[m]);
            acc[m] = fmaf(a.z, w2, acc[m]);
            acc[m] = fmaf(a.w, w3, acc[m]);
        }
    }
    const int lane = tid & 31, head = tid >> 5;
    const float asw = att_s[tid], adw = att_d[tid];
#pragma unroll
    for (int m = 0; m < BM; m++) {
        int r = row0 + m;
        float a = acc[m];
        float s = a * asw, d = a * adw;
#pragma unroll
        for (int o = 16; o > 0; o >>= 1) {
            s += __shfl_xor_sync(0xffffffffu, s, o);
            d += __shfl_xor_sync(0xffffffffu, d, o);
        }
        if (r < kN) {
            if (lane == 0) { SA[r * 16 + head] = s; SA[r * 16 + 8 + head] = d; }
            R16[(size_t)r * kHID1 + tid] = __float2half(a);
        }
    }
}

// ---------------- layer-1 aggregation stage h (head h = cols [32h,32h+32)) ---
// Warp per dst node; register accumulation; denominator fused; normalize+bias+
// elu fused; writes x1 slice into previous (dead) slice (h==0 -> g_x1a spare).
__global__ __launch_bounds__(256) void agg1_stage_kernel(const float* __restrict__ SA,
                                                         const float* __restrict__ b1,
                                                         __half* R16, int h) {
    int w = (blockIdx.x * blockDim.x + threadIdx.x) >> 5;
    int lane = threadIdx.x & 31;
    if (w >= kN) return;
    int beg = g_rowptr[w], end = g_rowptr[w + 1];
    float ad = SA[w * 16 + 8 + h];
    float acc = 0.f, dsum = 0.f;
    for (int j = beg; j < end; j++) {
        int src = g_src16[j];
        float e = expf(lrelu(SA[src * 16 + h] + ad));
        float hv = __half2float(R16[(size_t)src * kHID1 + h * 32 + lane]);
        acc = fmaf(e, hv, acc);
        dsum += e;
    }
    float xv = acc / (dsum + 1e-16f) + b1[h * 32 + lane];
    xv = xv > 0.f ? xv : expm1f(xv);
    __half hx = __float2half(xv);
    if (h == 0) g_x1a[w * 32 + lane] = hx;
    else        R16[(size_t)w * kHID1 + (h - 1) * 32 + lane] = hx;
    if (lane == 0) g_d1[w * 8 + h] = dsum;
}

// ---------------- GEMM2: h2 = x1 @ W2 + fused as2/ad2; h2 -> R16 cols[0:128) -
// BM=32 rows, 128 threads (one per col). x1 gathered from g_x1a + shifted R16.
__global__ __launch_bounds__(128) void gemm2_kernel(const float* __restrict__ W2,
                                                    const float* __restrict__ att_s,
                                                    const float* __restrict__ att_d,
                                                    __half* R16) {
    const int BM = 32, K = kHID1, CO = kHID2;
    __shared__ __half As[BM * K];   // 16 KB
    __shared__ float redS[4][BM], redD[4][BM];
    const int tid = threadIdx.x;
    const int row0 = blockIdx.x * BM;
    // stage x1: col c<32 from g_x1a[r*32+c]; c>=32 from R16[r*256 + c-32]
    for (int i = tid; i < BM * (K / 8); i += 128) {     // 1024 uint4 loads
        int row = i >> 5, c8 = i & 31;
        int r = row0 + row;
        uint4 v = make_uint4(0u, 0u, 0u, 0u);
        if (r < kN) {
            if (c8 < 4) v = *(const uint4*)(g_x1a + (size_t)r * 32 + c8 * 8);
            else        v = *(const uint4*)(R16 + (size_t)r * kHID1 + c8 * 8 - 32);
        }
        *(uint4*)&As[row * K + c8 * 8] = v;
    }
    __syncthreads();

    float acc[BM];
#pragma unroll
    for (int m = 0; m < BM; m++) acc[m] = 0.f;
    for (int k2 = 0; k2 < K / 2; k2++) {
        float w0 = W2[(2 * k2 + 0) * CO + tid];
        float w1 = W2[(2 * k2 + 1) * CO + tid];
#pragma unroll
        for (int m = 0; m < BM; m++) {
            float2 a = __half22float2(*(const __half2*)&As[m * K + 2 * k2]);
            acc[m] = fmaf(a.x, w0, acc[m]);
            acc[m] = fmaf(a.y, w1, acc[m]);
        }
    }
    const int lane = tid & 31, warp = tid >> 5;
    const float asw = att_s[tid], adw = att_d[tid];
#pragma unroll
    for (int m = 0; m < BM; m++) {
        float s = acc[m] * asw, d = acc[m] * adw;
#pragma unroll
        for (int o = 16; o > 0; o >>= 1) {
            s += __shfl_xor_sync(0xffffffffu, s, o);
            d += __shfl_xor_sync(0xffffffffu, d, o);
        }
        if (lane == 0) { redS[warp][m] = s; redD[warp][m] = d; }
    }
    __syncthreads();
    if (tid < BM) {
        int r = row0 + tid;
        if (r < kN) {
            g_as2[r] = redS[0][tid] + redS[1][tid] + redS[2][tid] + redS[3][tid];
            g_ad2[r] = redD[0][tid] + redD[1][tid] + redD[2][tid] + redD[3][tid];
        }
    }
#pragma unroll
    for (int m = 0; m < BM; m++) {
        int r = row0 + m;
        if (r < kN) R16[(size_t)r * kHID1 + tid] = __float2half(acc[m]);  // own rows only
    }
}

// ---------------- layer-2 aggregation: warp per node, single pass ------------
// Reads h2 (R16 cols [0:128)), writes x2 fp16 -> R16 cols [128:256); fused
// denominator + relu + bias.
__global__ __launch_bounds__(256) void agg2_kernel(const float* __restrict__ b2,
                                                   __half* R16) {
    int w = (blockIdx.x * blockDim.x + threadIdx.x) >> 5;
    int lane = threadIdx.x & 31;
    if (w >= kN) return;
    int beg = g_rowptr[w], end = g_rowptr[w + 1];
    float ad = g_ad2[w];
    float a0 = 0.f, a1 = 0.f, a2 = 0.f, a3 = 0.f, dsum = 0.f;
    for (int j = beg; j < end; j++) {
        int src = g_src16[j];
        float e = expf(lrelu(g_as2[src] + ad));
        uint2 hv = *(const uint2*)(R16 + (size_t)src * kHID1 + lane * 4);
        float2 f0 = __half22float2(*(const __half2*)&hv.x);
        float2 f1 = __half22float2(*(const __half2*)&hv.y);
        a0 = fmaf(e, f0.x, a0); a1 = fmaf(e, f0.y, a1);
        a2 = fmaf(e, f1.x, a2); a3 = fmaf(e, f1.y, a3);
        dsum += e;
    }
    float inv = 1.f / (dsum + 1e-16f);
    float4 bb = *(const float4*)(b2 + lane * 4);
    a0 = fmaxf(fmaf(a0, inv, bb.x), 0.f);
    a1 = fmaxf(fmaf(a1, inv, bb.y), 0.f);
    a2 = fmaxf(fmaf(a2, inv, bb.z), 0.f);
    a3 = fmaxf(fmaf(a3, inv, bb.w), 0.f);
    __half2 o0 = __floats2half2_rn(a0, a1), o1 = __floats2half2_rn(a2, a3);
    uint2 o;
    o.x = *(unsigned int*)&o0; o.y = *(unsigned int*)&o1;
    *(uint2*)(R16 + (size_t)w * kHID1 + 128 + lane * 4) = o;
    if (lane == 0) g_d2[w] = dsum;
}

// ---------------- fused FC head: out = relu(x2@fcW1+fcb1)@fcW2+fcb2 ----------
// BM=32 rows, 512 threads (one per FC1 col). x2 fp16 at R16 cols [128:256).
__global__ __launch_bounds__(512) void fc_kernel(const __half* __restrict__ R16,
                                                 const float* __restrict__ fcW1,
                                                 const float* __restrict__ fcb1,
                                                 const float* __restrict__ fcW2,
                                                 const float* __restrict__ fcb2,
                                                 float* __restrict__ out) {
    const int BM = 32;
    __shared__ float Xs[BM * kHID2];   // 16 KB
    __shared__ float wsum[16][BM];     // 2 KB
    const int tid = threadIdx.x;
    const int row0 = blockIdx.x * BM;

    {   // 512 loads: row = tid>>4, 8 halves each
        int row = tid >> 4, c16 = tid & 15;
        int r = row0 + row;
        uint4 raw = make_uint4(0u, 0u, 0u, 0u);
        if (r < kN) raw = *(const uint4*)(R16 + (size_t)r * kHID1 + 128 + c16 * 8);
        const __half2* hp = (const __half2*)&raw;
#pragma unroll
        for (int j2 = 0; j2 < 4; j2++) {
            float2 f = __half22float2(hp[j2]);
            Xs[row * kHID2 + c16 * 8 + 2 * j2]     = f.x;
            Xs[row * kHID2 + c16 * 8 + 2 * j2 + 1] = f.y;
        }
    }
    __syncthreads();

    float acc[BM];
#pragma unroll
    for (int m = 0; m < BM; m++) acc[m] = 0.f;
    for (int k = 0; k < kHID2; k += 4) {
        float w0 = fcW1[(k + 0) * kFC1 + tid];
        float w1 = fcW1[(k + 1) * kFC1 + tid];
        float w2 = fcW1[(k + 2) * kFC1 + tid];
        float w3 = fcW1[(k + 3) * kFC1 + tid];
#pragma unroll
        for (int m = 0; m < BM; m++) {
            float4 a = *(const float4*)&Xs[m * kHID2 + k];
            acc[m] = fmaf(a.x, w0, acc[m]);
            acc[m] = fmaf(a.y, w1, acc[m]);
            acc[m] = fmaf(a.z, w2, acc[m]);
            acc[m] = fmaf(a.w, w3, acc[m]);
        }
    }
    float c = fcW2[tid], bb = fcb1[tid];
    const int warp = tid >> 5, lane = tid & 31;
#pragma unroll
    for (int m = 0; m < BM; m++) {
        float p = fmaxf(acc[m] + bb, 0.f) * c;
#pragma unroll
        for (int o = 16; o > 0; o >>= 1) p += __shfl_xor_sync(0xffffffffu, p, o);
        if (lane == 0) wsum[warp][m] = p;
    }
    __syncthreads();
    if (tid < BM) {
        float s = fcb2[0];
#pragma unroll
        for (int w2 = 0; w2 < 16; w2++) s += wsum[w2][tid];
        int r = row0 + tid;
        if (r < kN) out[r] = s;
    }
}

// ---------------- final alpha writes (alpha1 first: needs SA) ----------------
__global__ __launch_bounds__(256) void alpha1_write_kernel(const int* __restrict__ ei,
                                                           const float* __restrict__ SA,
                                                           float* __restrict__ alpha1) {
    int e = blockIdx.x * blockDim.x + threadIdx.x;
    if (e >= kE) return;
    int src = ei[e], dst = ei[kE + e];
    float4 as0 = ((const float4*)(SA + src * 16))[0];
    float4 as1 = ((const float4*)(SA + src * 16))[1];
    float4 ad0 = ((const float4*)(SA + dst * 16 + 8))[0];
    float4 ad1 = ((const float4*)(SA + dst * 16 + 8))[1];
    float4 d0 = ((const float4*)(g_d1 + dst * 8))[0];
    float4 d1 = ((const float4*)(g_d1 + dst * 8))[1];
    float4 r0, r1;
    r0.x = expf(lrelu(as0.x + ad0.x)) / (d0.x + 1e-16f);
    r0.y = expf(lrelu(as0.y + ad0.y)) / (d0.y + 1e-16f);
    r0.z = expf(lrelu(as0.z + ad0.z)) / (d0.z + 1e-16f);
    r0.w = expf(lrelu(as0.w + ad0.w)) / (d0.w + 1e-16f);
    r1.x = expf(lrelu(as1.x + ad1.x)) / (d1.x + 1e-16f);
    r1.y = expf(lrelu(as1.y + ad1.y)) / (d1.y + 1e-16f);
    r1.z = expf(lrelu(as1.z + ad1.z)) / (d1.z + 1e-16f);
    r1.w = expf(lrelu(as1.w + ad1.w)) / (d1.w + 1e-16f);
    ((float4*)(alpha1 + (size_t)e * 8))[0] = r0;
    ((float4*)(alpha1 + (size_t)e * 8))[1] = r1;
}

__global__ __launch_bounds__(256) void alpha2_write_kernel(const int* __restrict__ ei,
                                                           float* __restrict__ alpha2) {
    int e = blockIdx.x * blockDim.x + threadIdx.x;
    if (e >= kE) return;
    int src = ei[e], dst = ei[kE + e];
    alpha2[e] = expf(lrelu(g_as2[src] + g_ad2[dst])) / (g_d2[dst] + 1e-16f);
}

// ---------------- launch ----------------------------------------------------
extern "C" void kernel_launch(void* const* d_in, const int* in_sizes, int n_in,
                              void* d_out, int out_size) {
    const float* x        = (const float*)d_in[0];
    const int*   ei       = (const int*)d_in[1];
    const float* W1       = (const float*)d_in[2];
    const float* att_src1 = (const float*)d_in[3];
    const float* att_dst1 = (const float*)d_in[4];
    const float* b1       = (const float*)d_in[5];
    const float* W2       = (const float*)d_in[6];
    const float* att_src2 = (const float*)d_in[7];
    const float* att_dst2 = (const float*)d_in[8];
    const float* b2       = (const float*)d_in[9];
    const float* fcW1     = (const float*)d_in[10];
    const float* fcb1     = (const float*)d_in[11];
    const float* fcW2     = (const float*)d_in[12];
    const float* fcb2     = (const float*)d_in[13];

    float* out_o  = (float*)d_out;
    float* alpha1 = (float*)d_out + kN;
    float* alpha2 = (float*)d_out + kN + (size_t)kE * 8;
    __half* R16   = (__half*)alpha1;   // fp16 [kN,256] staging
    float*  SA    = alpha2;            // fp32 [kN,16]  as1|ad1

    const int TPB = 256;
    const int edge_blocks = (kE + TPB - 1) / TPB;      // 3125
    const int node_blocks = (kN + TPB - 1) / TPB;      // 196
    const int warp_blocks = (kN * 32 + TPB - 1) / TPB; // 6250 (warp per node)
    const int g1_blocks   = (kN + 31) / 32;            // 1563

    // CSR build + GEMM1
    init_cnt_kernel<<<node_blocks, TPB>>>();
    hist_kernel<<<edge_blocks, TPB>>>(ei);
    scan1_kernel<<<SCAN_B, TPB>>>();
    scan2_kernel<<<1, TPB>>>();
    scan3_kernel<<<SCAN_B, TPB>>>();
    fill_kernel<<<edge_blocks, TPB>>>(ei);
    gemm1_kernel<<<g1_blocks, 256>>>(x, W1, att_src1, att_dst1, R16, SA);

    // Layer-1 aggregation: 8 gather stages (head h), register accumulation
    for (int h = 0; h < 8; h++)
        agg1_stage_kernel<<<warp_blocks, TPB>>>(SA, b1, R16, h);

    // Layer 2
    gemm2_kernel<<<g1_blocks, 128>>>(W2, att_src2, att_dst2, R16);
    agg2_kernel<<<warp_blocks, TPB>>>(b2, R16);

    // FC head
    fc_kernel<<<g1_blocks, 512>>>(R16, fcW1, fcb1, fcW2, fcb2, out_o);

    // Final alpha outputs (alpha1 before alpha2: alpha1 reads SA)
    alpha1_write_kernel<<<edge_blocks, TPB>>>(ei, SA, alpha1);
    alpha2_write_kernel<<<edge_blocks, TPB>>>(ei, alpha2);
}

// round 15
// speedup vs baseline: 1.5471x; 1.1540x over previous
#include <cuda_runtime.h>
#include <cuda_fp16.h>
#include <math.h>

// Problem constants (fixed shapes)
#define kN    50000
#define kE    800000
#define kIN   128
#define kH1   8
#define kHID1 256
#define kHID2 128
#define kFC1  512
#define SCAN_B 196   // ceil(kN/256)

// ---------------- device globals: TOTAL = 10.6 MB ----------------------------
__device__ unsigned short g_src16[kE];     // 1.6 MB  CSR src ids (kN < 65536)
__device__ int   g_cnt[kN];                // 0.2 MB  histogram -> fill cursor
__device__ int   g_rowptr[kN + 1];         // 0.2 MB  CSR row pointers
__device__ int   g_bsum[SCAN_B];           //         scan block sums
__device__ float g_d1[kN * kH1];           // 1.6 MB  layer-1 denominators
__device__ float g_as2[kN];                // 0.6 MB  layer-2 scores + denom
__device__ float g_ad2[kN];
__device__ float g_d2[kN];
__device__ __align__(16) __half g_x1a[kN * 64];  // 6.4 MB spare slice (x1 cols [0:64))

// d_out layout: out [kN] | alpha1 region [kE*8 f32 = 25.6MB] | alpha2 region [kE f32 = 3.2MB]
// alpha1 region as fp16 R16[kN][256]:
//   h1 -> x1 (4 stages of 64 cols; stage s writes into slot s-1; stage 0 -> g_x1a)
//   -> h2 (cols [0:128), own rows) + x2 (cols [128:256)) -> finally alpha1 fp32.
// alpha2 region as fp32 SA[kN][16]: as1[8] | ad1[8] -> finally alpha2.

// ---------------- helpers ---------------------------------------------------
__device__ __forceinline__ float lrelu(float v) { return v > 0.f ? v : 0.2f * v; }

// ---------------- init: zero histogram --------------------------------------
__global__ __launch_bounds__(256) void init_cnt_kernel() {
    int i = blockIdx.x * blockDim.x + threadIdx.x;
    if (i < kN) g_cnt[i] = 0;
}

// ---------------- CSR build --------------------------------------------------
__global__ __launch_bounds__(256) void hist_kernel(const int* __restrict__ ei) {
    int e = blockIdx.x * blockDim.x + threadIdx.x;
    if (e >= kE) return;
    atomicAdd(&g_cnt[ei[kE + e]], 1);
}

__global__ __launch_bounds__(256) void scan1_kernel() {
    __shared__ int s[256];
    int t = threadIdx.x;
    int i = blockIdx.x * 256 + t;
    int v = (i < kN) ? g_cnt[i] : 0;
    s[t] = v; __syncthreads();
#pragma unroll
    for (int off = 1; off < 256; off <<= 1) {
        int x = (t >= off) ? s[t - off] : 0; __syncthreads();
        s[t] += x; __syncthreads();
    }
    if (i < kN) g_rowptr[i] = s[t] - v;
    if (t == 255) g_bsum[blockIdx.x] = s[255];
}

__global__ __launch_bounds__(256) void scan2_kernel() {
    __shared__ int s[256];
    int t = threadIdx.x;
    int v = (t < SCAN_B) ? g_bsum[t] : 0;
    s[t] = v; __syncthreads();
#pragma unroll
    for (int off = 1; off < 256; off <<= 1) {
        int x = (t >= off) ? s[t - off] : 0; __syncthreads();
        s[t] += x; __syncthreads();
    }
    if (t < SCAN_B) g_bsum[t] = s[t] - v;
}

__global__ __launch_bounds__(256) void scan3_kernel() {
    int i = blockIdx.x * 256 + threadIdx.x;
    if (i < kN) {
        int val = g_rowptr[i] + g_bsum[blockIdx.x];
        g_rowptr[i] = val;
        g_cnt[i] = val;
    }
    if (i == 0) g_rowptr[kN] = kE;
}

__global__ __launch_bounds__(256) void fill_kernel(const int* __restrict__ ei) {
    int e = blockIdx.x * blockDim.x + threadIdx.x;
    if (e >= kE) return;
    int src = ei[e], dst = ei[kE + e];
    int pos = atomicAdd(&g_cnt[dst], 1);
    g_src16[pos] = (unsigned short)src;
}

// ---------------- GEMM1: h1 = x @ W1 (fp16) + fused as1/ad1 into SA ----------
__global__ __launch_bounds__(256) void gemm1_kernel(const float* __restrict__ x,
                                                    const float* __restrict__ W1,
                                                    const float* __restrict__ att_s,
                                                    const float* __restrict__ att_d,
                                                    __half* __restrict__ R16,
                                                    float* __restrict__ SA) {
    const int BM = 32, K = kIN, CO = kHID1;
    __shared__ float As[BM * K];   // 16 KB
    const int tid = threadIdx.x;
    const int row0 = blockIdx.x * BM;
    for (int i = tid; i < BM * (K / 4); i += 256) {
        int m = i / (K / 4), c = i % (K / 4);
        int r = row0 + m;
        float4 v = make_float4(0.f, 0.f, 0.f, 0.f);
        if (r < kN) v = ((const float4*)x)[(size_t)r * (K / 4) + c];
        ((float4*)As)[i] = v;
    }
    __syncthreads();

    float acc[BM];
#pragma unroll
    for (int m = 0; m < BM; m++) acc[m] = 0.f;
    for (int k = 0; k < K; k += 4) {
        float w0 = W1[(k + 0) * CO + tid];
        float w1 = W1[(k + 1) * CO + tid];
        float w2 = W1[(k + 2) * CO + tid];
        float w3 = W1[(k + 3) * CO + tid];
#pragma unroll
        for (int m = 0; m < BM; m++) {
            float4 a = *(const float4*)&As[m * K + k];
            acc[m] = fmaf(a.x, w0, acc[m]);
            acc[m] = fmaf(a.y, w1, acc[m]);
            acc[m] = fmaf(a.z, w2, acc[m]);
            acc[m] = fmaf(a.w, w3, acc[m]);
        }
    }
    const int lane = tid & 31, head = tid >> 5;
    const float asw = att_s[tid], adw = att_d[tid];
#pragma unroll
    for (int m = 0; m < BM; m++) {
        int r = row0 + m;
        float a = acc[m];
        float s = a * asw, d = a * adw;
#pragma unroll
        for (int o = 16; o > 0; o >>= 1) {
            s += __shfl_xor_sync(0xffffffffu, s, o);
            d += __shfl_xor_sync(0xffffffffu, d, o);
        }
        if (r < kN) {
            if (lane == 0) { SA[r * 16 + head] = s; SA[r * 16 + 8 + head] = d; }
            R16[(size_t)r * kHID1 + tid] = __float2half(a);
        }
    }
}

// ---------------- layer-1 aggregation stage s: heads 2s,2s+1 (cols [64s,64s+64))
// Warp per dst node; lane L covers cols 64s+2L..+2 (head = 2s + L/16); register
// accumulation; denominator + normalize + bias + elu fused; x1 written into the
// previous (dead) 64-col slot (stage 0 -> g_x1a spare).
__global__ __launch_bounds__(256) void agg1_stage_kernel(const float* __restrict__ SA,
                                                         const float* __restrict__ b1,
                                                         __half* R16, int s) {
    int w = (blockIdx.x * blockDim.x + threadIdx.x) >> 5;
    int L = threadIdx.x & 31;
    if (w >= kN) return;
    int beg = g_rowptr[w], end = g_rowptr[w + 1];
    int head = 2 * s + (L >> 4);
    float ad = SA[w * 16 + 8 + head];
    float a0 = 0.f, a1 = 0.f, dsum = 0.f;
#pragma unroll 4
    for (int j = beg; j < end; j++) {
        int src = g_src16[j];
        float asv = SA[src * 16 + head];
        unsigned int hv = *(const unsigned int*)(R16 + (size_t)src * kHID1 + s * 64 + 2 * L);
        float e = expf(lrelu(asv + ad));
        float2 f = __half22float2(*(const __half2*)&hv);
        a0 = fmaf(e, f.x, a0);
        a1 = fmaf(e, f.y, a1);
        dsum += e;
    }
    float inv = 1.f / (dsum + 1e-16f);
    float xv0 = fmaf(a0, inv, b1[s * 64 + 2 * L]);
    float xv1 = fmaf(a1, inv, b1[s * 64 + 2 * L + 1]);
    xv0 = xv0 > 0.f ? xv0 : expm1f(xv0);
    xv1 = xv1 > 0.f ? xv1 : expm1f(xv1);
    __half2 hx = __floats2half2_rn(xv0, xv1);
    if (s == 0) *(unsigned int*)(g_x1a + w * 64 + 2 * L) = *(unsigned int*)&hx;
    else        *(unsigned int*)(R16 + (size_t)w * kHID1 + (s - 1) * 64 + 2 * L) = *(unsigned int*)&hx;
    if ((L & 15) == 0) g_d1[w * 8 + head] = dsum;
}

// ---------------- GEMM2: h2 = x1 @ W2 + fused as2/ad2; h2 -> R16 cols[0:128) -
// x1 layout: cols [0:64) in g_x1a; cols [64:256) at R16 cols [0:192).
__global__ __launch_bounds__(128) void gemm2_kernel(const float* __restrict__ W2,
                                                    const float* __restrict__ att_s,
                                                    const float* __restrict__ att_d,
                                                    __half* R16) {
    const int BM = 32, K = kHID1, CO = kHID2;
    __shared__ __half As[BM * K];   // 16 KB
    __shared__ float redS[4][BM], redD[4][BM];
    const int tid = threadIdx.x;
    const int row0 = blockIdx.x * BM;
    for (int i = tid; i < BM * (K / 8); i += 128) {     // 1024 uint4 loads
        int row = i >> 5, c8 = i & 31;
        int r = row0 + row;
        uint4 v = make_uint4(0u, 0u, 0u, 0u);
        if (r < kN) {
            if (c8 < 8) v = *(const uint4*)(g_x1a + (size_t)r * 64 + c8 * 8);
            else        v = *(const uint4*)(R16 + (size_t)r * kHID1 + (c8 - 8) * 8);
        }
        *(uint4*)&As[row * K + c8 * 8] = v;
    }
    __syncthreads();

    float acc[BM];
#pragma unroll
    for (int m = 0; m < BM; m++) acc[m] = 0.f;
    for (int k2 = 0; k2 < K / 2; k2++) {
        float w0 = W2[(2 * k2 + 0) * CO + tid];
        float w1 = W2[(2 * k2 + 1) * CO + tid];
#pragma unroll
        for (int m = 0; m < BM; m++) {
            float2 a = __half22float2(*(const __half2*)&As[m * K + 2 * k2]);
            acc[m] = fmaf(a.x, w0, acc[m]);
            acc[m] = fmaf(a.y, w1, acc[m]);
        }
    }
    const int lane = tid & 31, warp = tid >> 5;
    const float asw = att_s[tid], adw = att_d[tid];
#pragma unroll
    for (int m = 0; m < BM; m++) {
        float s = acc[m] * asw, d = acc[m] * adw;
#pragma unroll
        for (int o = 16; o > 0; o >>= 1) {
            s += __shfl_xor_sync(0xffffffffu, s, o);
            d += __shfl_xor_sync(0xffffffffu, d, o);
        }
        if (lane == 0) { redS[warp][m] = s; redD[warp][m] = d; }
    }
    __syncthreads();
    if (tid < BM) {
        int r = row0 + tid;
        if (r < kN) {
            g_as2[r] = redS[0][tid] + redS[1][tid] + redS[2][tid] + redS[3][tid];
            g_ad2[r] = redD[0][tid] + redD[1][tid] + redD[2][tid] + redD[3][tid];
        }
    }
#pragma unroll
    for (int m = 0; m < BM; m++) {
        int r = row0 + m;
        if (r < kN) R16[(size_t)r * kHID1 + tid] = __float2half(acc[m]);  // own rows only
    }
}

// ---------------- layer-2 aggregation: warp per node, single pass ------------
__global__ __launch_bounds__(256) void agg2_kernel(const float* __restrict__ b2,
                                                   __half* R16) {
    int w = (blockIdx.x * blockDim.x + threadIdx.x) >> 5;
    int lane = threadIdx.x & 31;
    if (w >= kN) return;
    int beg = g_rowptr[w], end = g_rowptr[w + 1];
    float ad = g_ad2[w];
    float a0 = 0.f, a1 = 0.f, a2 = 0.f, a3 = 0.f, dsum = 0.f;
#pragma unroll 4
    for (int j = beg; j < end; j++) {
        int src = g_src16[j];
        float e = expf(lrelu(g_as2[src] + ad));
        uint2 hv = *(const uint2*)(R16 + (size_t)src * kHID1 + lane * 4);
        float2 f0 = __half22float2(*(const __half2*)&hv.x);
        float2 f1 = __half22float2(*(const __half2*)&hv.y);
        a0 = fmaf(e, f0.x, a0); a1 = fmaf(e, f0.y, a1);
        a2 = fmaf(e, f1.x, a2); a3 = fmaf(e, f1.y, a3);
        dsum += e;
    }
    float inv = 1.f / (dsum + 1e-16f);
    float4 bb = *(const float4*)(b2 + lane * 4);
    a0 = fmaxf(fmaf(a0, inv, bb.x), 0.f);
    a1 = fmaxf(fmaf(a1, inv, bb.y), 0.f);
    a2 = fmaxf(fmaf(a2, inv, bb.z), 0.f);
    a3 = fmaxf(fmaf(a3, inv, bb.w), 0.f);
    __half2 o0 = __floats2half2_rn(a0, a1), o1 = __floats2half2_rn(a2, a3);
    uint2 o;
    o.x = *(unsigned int*)&o0; o.y = *(unsigned int*)&o1;
    *(uint2*)(R16 + (size_t)w * kHID1 + 128 + lane * 4) = o;
    if (lane == 0) g_d2[w] = dsum;
}

// ---------------- fused FC head: out = relu(x2@fcW1+fcb1)@fcW2+fcb2 ----------
__global__ __launch_bounds__(512) void fc_kernel(const __half* __restrict__ R16,
                                                 const float* __restrict__ fcW1,
                                                 const float* __restrict__ fcb1,
                                                 const float* __restrict__ fcW2,
                                                 const float* __restrict__ fcb2,
                                                 float* __restrict__ out) {
    const int BM = 32;
    __shared__ float Xs[BM * kHID2];   // 16 KB
    __shared__ float wsum[16][BM];     // 2 KB
    const int tid = threadIdx.x;
    const int row0 = blockIdx.x * BM;

    {
        int row = tid >> 4, c16 = tid & 15;
        int r = row0 + row;
        uint4 raw = make_uint4(0u, 0u, 0u, 0u);
        if (r < kN) raw = *(const uint4*)(R16 + (size_t)r * kHID1 + 128 + c16 * 8);
        const __half2* hp = (const __half2*)&raw;
#pragma unroll
        for (int j2 = 0; j2 < 4; j2++) {
            float2 f = __half22float2(hp[j2]);
            Xs[row * kHID2 + c16 * 8 + 2 * j2]     = f.x;
            Xs[row * kHID2 + c16 * 8 + 2 * j2 + 1] = f.y;
        }
    }
    __syncthreads();

    float acc[BM];
#pragma unroll
    for (int m = 0; m < BM; m++) acc[m] = 0.f;
    for (int k = 0; k < kHID2; k += 4) {
        float w0 = fcW1[(k + 0) * kFC1 + tid];
        float w1 = fcW1[(k + 1) * kFC1 + tid];
        float w2 = fcW1[(k + 2) * kFC1 + tid];
        float w3 = fcW1[(k + 3) * kFC1 + tid];
#pragma unroll
        for (int m = 0; m < BM; m++) {
            float4 a = *(const float4*)&Xs[m * kHID2 + k];
            acc[m] = fmaf(a.x, w0, acc[m]);
            acc[m] = fmaf(a.y, w1, acc[m]);
            acc[m] = fmaf(a.z, w2, acc[m]);
            acc[m] = fmaf(a.w, w3, acc[m]);
        }
    }
    float c = fcW2[tid], bb = fcb1[tid];
    const int warp = tid >> 5, lane = tid & 31;
#pragma unroll
    for (int m = 0; m < BM; m++) {
        float p = fmaxf(acc[m] + bb, 0.f) * c;
#pragma unroll
        for (int o = 16; o > 0; o >>= 1) p += __shfl_xor_sync(0xffffffffu, p, o);
        if (lane == 0) wsum[warp][m] = p;
    }
    __syncthreads();
    if (tid < BM) {
        float s = fcb2[0];
#pragma unroll
        for (int w2 = 0; w2 < 16; w2++) s += wsum[w2][tid];
        int r = row0 + tid;
        if (r < kN) out[r] = s;
    }
}

// ---------------- final alpha writes (alpha1 first: needs SA) ----------------
__global__ __launch_bounds__(256) void alpha1_write_kernel(const int* __restrict__ ei,
                                                           const float* __restrict__ SA,
                                                           float* __restrict__ alpha1) {
    int e = blockIdx.x * blockDim.x + threadIdx.x;
    if (e >= kE) return;
    int src = ei[e], dst = ei[kE + e];
    float4 as0 = ((const float4*)(SA + src * 16))[0];
    float4 as1 = ((const float4*)(SA + src * 16))[1];
    float4 ad0 = ((const float4*)(SA + dst * 16 + 8))[0];
    float4 ad1 = ((const float4*)(SA + dst * 16 + 8))[1];
    float4 d0 = ((const float4*)(g_d1 + dst * 8))[0];
    float4 d1 = ((const float4*)(g_d1 + dst * 8))[1];
    float4 r0, r1;
    r0.x = expf(lrelu(as0.x + ad0.x)) / (d0.x + 1e-16f);
    r0.y = expf(lrelu(as0.y + ad0.y)) / (d0.y + 1e-16f);
    r0.z = expf(lrelu(as0.z + ad0.z)) / (d0.z + 1e-16f);
    r0.w = expf(lrelu(as0.w + ad0.w)) / (d0.w + 1e-16f);
    r1.x = expf(lrelu(as1.x + ad1.x)) / (d1.x + 1e-16f);
    r1.y = expf(lrelu(as1.y + ad1.y)) / (d1.y + 1e-16f);
    r1.z = expf(lrelu(as1.z + ad1.z)) / (d1.z + 1e-16f);
    r1.w = expf(lrelu(as1.w + ad1.w)) / (d1.w + 1e-16f);
    ((float4*)(alpha1 + (size_t)e * 8))[0] = r0;
    ((float4*)(alpha1 + (size_t)e * 8))[1] = r1;
}

__global__ __launch_bounds__(256) void alpha2_write_kernel(const int* __restrict__ ei,
                                                           float* __restrict__ alpha2) {
    int e = blockIdx.x * blockDim.x + threadIdx.x;
    if (e >= kE) return;
    int src = ei[e], dst = ei[kE + e];
    alpha2[e] = expf(lrelu(g_as2[src] + g_ad2[dst])) / (g_d2[dst] + 1e-16f);
}

// ---------------- launch ----------------------------------------------------
extern "C" void kernel_launch(void* const* d_in, const int* in_sizes, int n_in,
                              void* d_out, int out_size) {
    const float* x        = (const float*)d_in[0];
    const int*   ei       = (const int*)d_in[1];
    const float* W1       = (const float*)d_in[2];
    const float* att_src1 = (const float*)d_in[3];
    const float* att_dst1 = (const float*)d_in[4];
    const float* b1       = (const float*)d_in[5];
    const float* W2       = (const float*)d_in[6];
    const float* att_src2 = (const float*)d_in[7];
    const float* att_dst2 = (const float*)d_in[8];
    const float* b2       = (const float*)d_in[9];
    const float* fcW1     = (const float*)d_in[10];
    const float* fcb1     = (const float*)d_in[11];
    const float* fcW2     = (const float*)d_in[12];
    const float* fcb2     = (const float*)d_in[13];

    float* out_o  = (float*)d_out;
    float* alpha1 = (float*)d_out + kN;
    float* alpha2 = (float*)d_out + kN + (size_t)kE * 8;
    __half* R16   = (__half*)alpha1;   // fp16 [kN,256] staging
    float*  SA    = alpha2;            // fp32 [kN,16]  as1|ad1

    const int TPB = 256;
    const int edge_blocks = (kE + TPB - 1) / TPB;      // 3125
    const int node_blocks = (kN + TPB - 1) / TPB;      // 196
    const int warp_blocks = (kN * 32 + TPB - 1) / TPB; // 6250 (warp per node)
    const int g1_blocks   = (kN + 31) / 32;            // 1563

    // CSR build + GEMM1
    init_cnt_kernel<<<node_blocks, TPB>>>();
    hist_kernel<<<edge_blocks, TPB>>>(ei);
    scan1_kernel<<<SCAN_B, TPB>>>();
    scan2_kernel<<<1, TPB>>>();
    scan3_kernel<<<SCAN_B, TPB>>>();
    fill_kernel<<<edge_blocks, TPB>>>(ei);
    gemm1_kernel<<<g1_blocks, 256>>>(x, W1, att_src1, att_dst1, R16, SA);

    // Layer-1 aggregation: 4 gather stages (2 heads each), register accumulation
    for (int s = 0; s < 4; s++)
        agg1_stage_kernel<<<warp_blocks, TPB>>>(SA, b1, R16, s);

    // Layer 2
    gemm2_kernel<<<g1_blocks, 128>>>(W2, att_src2, att_dst2, R16);
    agg2_kernel<<<warp_blocks, TPB>>>(b2, R16);

    // FC head
    fc_kernel<<<g1_blocks, 512>>>(R16, fcW1, fcb1, fcW2, fcb2, out_o);

    // Final alpha outputs (alpha1 before alpha2: alpha1 reads SA)
    alpha1_write_kernel<<<edge_blocks, TPB>>>(ei, SA, alpha1);
    alpha2_write_kernel<<<edge_blocks, TPB>>>(ei, alpha2);
}